// round 12
// baseline (speedup 1.0000x reference)
#include <cuda_runtime.h>
#include <cuda_bf16.h>
#include <cuda_fp16.h>
#include <cstdint>

#define MAX_NODES 50000
#define MAX_EDGES 640000
#define CH 128
#define SCAN_CHUNK 1024

// ---------------- scratch (no allocs allowed -> device globals) -------------
__device__ __half g_xh[(size_t)MAX_NODES * CH];          // x in fp16 (gather src)
__device__ __nv_bfloat16 g_hhi[(size_t)MAX_NODES * CH];
__device__ __nv_bfloat16 g_hlo[(size_t)MAX_NODES * CH];
__device__ __nv_bfloat16 g_whi[CH * CH];
__device__ __nv_bfloat16 g_wlo[CH * CH];
__device__ int g_count[MAX_NODES + 4];
__device__ int g_start[MAX_NODES + 4];
__device__ int g_epos[MAX_EDGES];
__device__ int g_scol[MAX_EDGES];
__device__ int g_bsum[128];
__device__ int g_boff[128];
__device__ int g_done;

// ---------------- kernel A: fused init ---------------------------------------
// tasks (flat thread index i over full grid):
//   i < n_nodes*32 : convert x float4 -> half2x2  (4 elems per thread)
//   i < n_nodes+4  : zero g_count
//   i < CH*CH      : W hi/lo split
//   i == 0         : reset g_done
__global__ void init_kernel(const float* __restrict__ x,
                            const float* __restrict__ W, int n_nodes) {
    int i = blockIdx.x * blockDim.x + threadIdx.x;
    int n4 = n_nodes * (CH / 4);
    if (i < n4) {
        float4 v = reinterpret_cast<const float4*>(x)[i];
        uint2 p;
        __half2 h01 = __floats2half2_rn(v.x, v.y);
        __half2 h23 = __floats2half2_rn(v.z, v.w);
        p.x = *reinterpret_cast<uint32_t*>(&h01);
        p.y = *reinterpret_cast<uint32_t*>(&h23);
        reinterpret_cast<uint2*>(g_xh)[i] = p;
    }
    if (i < n_nodes + 4) g_count[i] = 0;
    if (i < CH * CH) {
        float w = W[i];
        __nv_bfloat16 hi = __float2bfloat16(w);
        g_whi[i] = hi;
        g_wlo[i] = __float2bfloat16(w - __bfloat162float(hi));
    }
    if (i == 0) g_done = 0;
}

// ---------------- kernel 2: histogram + record intra-segment position --------
__global__ void hist_kernel(const int* __restrict__ edge_index, int n_edges) {
    int e = blockIdx.x * blockDim.x + threadIdx.x;
    if (e < n_edges) {
        int r = __ldg(&edge_index[e]);
        g_epos[e] = atomicAdd(&g_count[r], 1);
    }
}

// ---------------- kernel 3: partial sums + fused block-sum scan --------------
__global__ void partial_kernel(int n_nodes, int nblk) {
    __shared__ int wsum[8];
    __shared__ int sh_last;
    __shared__ int sh[128];
    int t = threadIdx.x;
    int base = blockIdx.x * SCAN_CHUNK + t * 4;
    int s = 0;
    if (base < n_nodes) {
        int4 v = *reinterpret_cast<const int4*>(&g_count[base]);
        s = v.x;
        if (base + 1 < n_nodes) s += v.y;
        if (base + 2 < n_nodes) s += v.z;
        if (base + 3 < n_nodes) s += v.w;
    }
#pragma unroll
    for (int o = 16; o > 0; o >>= 1) s += __shfl_down_sync(0xffffffffu, s, o);
    if ((t & 31) == 0) wsum[t >> 5] = s;
    __syncthreads();
    if (t < 8) {
        int v = wsum[t];
#pragma unroll
        for (int o = 4; o > 0; o >>= 1) v += __shfl_down_sync(0xffu, v, o);
        if (t == 0) {
            g_bsum[blockIdx.x] = v;
            __threadfence();
            int old = atomicAdd(&g_done, 1);
            sh_last = (old == nblk - 1) ? 1 : 0;
        }
    }
    __syncthreads();
    if (sh_last) {   // last finishing block scans the block sums (block-uniform)
        int v = (t < nblk && t < 128) ? g_bsum[t] : 0;
        if (t < 128) sh[t] = v;
        __syncthreads();
#pragma unroll
        for (int o = 1; o < 128; o <<= 1) {
            int x = (t < 128 && t >= o) ? sh[t - o] : 0;
            __syncthreads();
            if (t < 128) sh[t] += x;
            __syncthreads();
        }
        if (t < nblk && t < 128) g_boff[t] = sh[t] - v;
    }
}

// ---------------- kernel 4: final per-block exclusive scan -> g_start --------
__global__ void scan_final_kernel(int n_nodes) {
    __shared__ int woff[8];
    int t = threadIdx.x;
    int lane = t & 31;
    int w = t >> 5;
    int base = blockIdx.x * SCAN_CHUNK + t * 4;

    int4 c = make_int4(0, 0, 0, 0);
    if (base < n_nodes) {
        c = *reinterpret_cast<const int4*>(&g_count[base]);
        if (base + 1 >= n_nodes) c.y = 0;
        if (base + 2 >= n_nodes) c.z = 0;
        if (base + 3 >= n_nodes) c.w = 0;
    }
    int tot = c.x + c.y + c.z + c.w;

    int incl = tot;
#pragma unroll
    for (int o = 1; o < 32; o <<= 1) {
        int nv = __shfl_up_sync(0xffffffffu, incl, o);
        if (lane >= o) incl += nv;
    }
    if (lane == 31) woff[w] = incl;
    __syncthreads();
    if (t < 8) {
        int v = woff[t];
        int s = v;
#pragma unroll
        for (int o = 1; o < 8; o <<= 1) {
            int nv = __shfl_up_sync(0xffu, s, o);
            if (t >= o) s += nv;
        }
        woff[t] = s - v;
    }
    __syncthreads();

    int off = g_boff[blockIdx.x] + woff[w] + (incl - tot);
    if (base < n_nodes) {
        int4 st;
        st.x = off;
        st.y = off + c.x;
        st.z = off + c.x + c.y;
        st.w = off + c.x + c.y + c.z;
        *reinterpret_cast<int4*>(&g_start[base]) = st;
    }
}

// ---------------- kernel 5: atomic-free scatter into dest-sorted order -------
__global__ void scatter_idx_kernel(const int* __restrict__ edge_index, int n_edges) {
    int e = blockIdx.x * blockDim.x + threadIdx.x;
    if (e < n_edges) {
        int r = __ldg(&edge_index[e]);
        int c = __ldg(&edge_index[n_edges + e]);
        g_scol[__ldg(&g_start[r]) + g_epos[e]] = c;
    }
}

// ---------------- kernel 6: aggregation with fp16 gather ---------------------
// one warp per node; lane owns 4 channels; gathers neighbor rows in fp16
// (halved traffic), accumulates fp32, residual x in fp32, emits bf16 hi/lo.
__global__ __launch_bounds__(256)
void agg_kernel(const float* __restrict__ x, int n_nodes) {
    int gtid = blockIdx.x * blockDim.x + threadIdx.x;
    int node = gtid >> 5;
    int lane = threadIdx.x & 31;
    if (node >= n_nodes) return;

    const uint2* xh2 = reinterpret_cast<const uint2*>(g_xh);   // 4 halves / uint2
    const float4* x4 = reinterpret_cast<const float4*>(x);

    int s = g_start[node];
    int d = g_count[node];

    float4 acc = make_float4(0.f, 0.f, 0.f, 0.f);
    int j = 0;
    for (; j + 1 < d; j += 2) {
        int c0 = __ldg(&g_scol[s + j]);
        int c1 = __ldg(&g_scol[s + j + 1]);
        uint2 p0 = xh2[(size_t)c0 * 32 + lane];
        uint2 p1 = xh2[(size_t)c1 * 32 + lane];
        float2 a0 = __half22float2(*reinterpret_cast<__half2*>(&p0.x));
        float2 b0 = __half22float2(*reinterpret_cast<__half2*>(&p0.y));
        float2 a1 = __half22float2(*reinterpret_cast<__half2*>(&p1.x));
        float2 b1 = __half22float2(*reinterpret_cast<__half2*>(&p1.y));
        acc.x += a0.x + a1.x;
        acc.y += a0.y + a1.y;
        acc.z += b0.x + b1.x;
        acc.w += b0.y + b1.y;
    }
    if (j < d) {
        int c0 = __ldg(&g_scol[s + j]);
        uint2 p0 = xh2[(size_t)c0 * 32 + lane];
        float2 a0 = __half22float2(*reinterpret_cast<__half2*>(&p0.x));
        float2 b0 = __half22float2(*reinterpret_cast<__half2*>(&p0.y));
        acc.x += a0.x; acc.y += a0.y; acc.z += b0.x; acc.w += b0.y;
    }

    float inv = 1.f / (float)(d < 1 ? 1 : d);
    float4 xv = x4[(size_t)node * (CH / 4) + lane];
    float h0 = xv.x + acc.x * inv;
    float h1 = xv.y + acc.y * inv;
    float h2 = xv.z + acc.z * inv;
    float h3 = xv.w + acc.w * inv;

    __nv_bfloat16 b0 = __float2bfloat16(h0);
    __nv_bfloat16 b1 = __float2bfloat16(h1);
    __nv_bfloat16 b2 = __float2bfloat16(h2);
    __nv_bfloat16 b3 = __float2bfloat16(h3);
    __nv_bfloat16 l0 = __float2bfloat16(h0 - __bfloat162float(b0));
    __nv_bfloat16 l1 = __float2bfloat16(h1 - __bfloat162float(b1));
    __nv_bfloat16 l2 = __float2bfloat16(h2 - __bfloat162float(b2));
    __nv_bfloat16 l3 = __float2bfloat16(h3 - __bfloat162float(b3));

    __nv_bfloat162* hhi2 = reinterpret_cast<__nv_bfloat162*>(g_hhi);
    __nv_bfloat162* hlo2 = reinterpret_cast<__nv_bfloat162*>(g_hlo);
    size_t base = (size_t)node * (CH / 2) + lane * 2;
    hhi2[base + 0] = __halves2bfloat162(b0, b1);
    hhi2[base + 1] = __halves2bfloat162(b2, b3);
    hlo2[base + 0] = __halves2bfloat162(l0, l1);
    hlo2[base + 1] = __halves2bfloat162(l2, l3);
}

// ---------------- kernel 7: HMMA bf16-split GEMM (proven R10) ----------------
#define OFF_AHI 0
#define OFF_ALO 32768
#define OFF_WHI 65536
#define OFF_WLO 98304
#define OFF_BIAS 131072
#define SMEM_DYN (131072 + 512)

__device__ __forceinline__ uint32_t smem_u32(const void* p) {
    uint32_t a;
    asm("{ .reg .u64 t; cvta.to.shared.u64 t, %1; cvt.u32.u64 %0, t; }" : "=r"(a) : "l"(p));
    return a;
}

__device__ __forceinline__ void ldsm_x4(uint32_t* r, uint32_t addr) {
    asm volatile("ldmatrix.sync.aligned.m8n8.x4.shared.b16 {%0,%1,%2,%3}, [%4];"
                 : "=r"(r[0]), "=r"(r[1]), "=r"(r[2]), "=r"(r[3]) : "r"(addr));
}

__device__ __forceinline__ void mma_bf16(float* d, const uint32_t* a, uint32_t b0, uint32_t b1) {
    asm volatile(
        "mma.sync.aligned.m16n8k16.row.col.f32.bf16.bf16.f32 "
        "{%0,%1,%2,%3}, {%4,%5,%6,%7}, {%8,%9}, {%0,%1,%2,%3};"
        : "+f"(d[0]), "+f"(d[1]), "+f"(d[2]), "+f"(d[3])
        : "r"(a[0]), "r"(a[1]), "r"(a[2]), "r"(a[3]), "r"(b0), "r"(b1));
}

__global__ __launch_bounds__(256, 1)
void gemm_mma_kernel(const float* __restrict__ bias, float* __restrict__ out, int M) {
    extern __shared__ char sm[];
    uint32_t sbase = smem_u32(sm);

    int tid = threadIdx.x;
    int wid = tid >> 5;
    int lane = tid & 31;
    int row0 = blockIdx.x * 128;

    const uint4* hhi4 = reinterpret_cast<const uint4*>(g_hhi);
    const uint4* hlo4 = reinterpret_cast<const uint4*>(g_hlo);
    const uint4* whi4 = reinterpret_cast<const uint4*>(g_whi);
    const uint4* wlo4 = reinterpret_cast<const uint4*>(g_wlo);
    const uint4 zero4 = make_uint4(0, 0, 0, 0);

#pragma unroll 4
    for (int i = tid; i < 2048; i += 256) {
        int row = i >> 4;
        int c = i & 15;
        uint32_t sw = (uint32_t)row * 256 + (uint32_t)((c ^ (row & 7)) << 4);
        int gr = row0 + row;
        uint4 vh = zero4, vl = zero4;
        if (gr < M) {
            size_t gidx = (size_t)gr * 16 + c;
            vh = hhi4[gidx];
            vl = hlo4[gidx];
        }
        *reinterpret_cast<uint4*>(sm + OFF_AHI + sw) = vh;
        *reinterpret_cast<uint4*>(sm + OFF_ALO + sw) = vl;
        size_t widx = (size_t)row * 16 + c;
        *reinterpret_cast<uint4*>(sm + OFF_WHI + sw) = whi4[widx];
        *reinterpret_cast<uint4*>(sm + OFF_WLO + sw) = wlo4[widx];
    }
    if (tid < CH) *reinterpret_cast<float*>(sm + OFF_BIAS + tid * 4) = bias[tid];
    __syncthreads();

    int m_w = (wid & 3) * 32;
    int n_w = (wid >> 2) * 64;

    int jr = lane & 7;
    int a_row_in = (((lane >> 3) & 1) << 3) + jr;
    int a_csel = lane >> 4;
    int b_row_in = ((lane >> 4) << 3) + jr;
    int b_csel = (lane >> 3) & 1;

    float d[2][8][4];
#pragma unroll
    for (int mi = 0; mi < 2; mi++)
#pragma unroll
        for (int ni = 0; ni < 8; ni++)
#pragma unroll
            for (int k = 0; k < 4; k++) d[mi][ni][k] = 0.f;

#pragma unroll
    for (int t = 0; t < 3; t++) {
        uint32_t Abase = sbase + (t == 2 ? OFF_ALO : OFF_AHI);
        uint32_t Bbase = sbase + (t == 1 ? OFF_WLO : OFF_WHI);
#pragma unroll
        for (int s = 0; s < 8; s++) {
            uint32_t a[2][4];
#pragma unroll
            for (int mi = 0; mi < 2; mi++) {
                int row = m_w + mi * 16 + a_row_in;
                int chunk = 2 * s + a_csel;
                ldsm_x4(a[mi], Abase + row * 256 + ((chunk ^ jr) << 4));
            }
            uint32_t bf[4][4];
#pragma unroll
            for (int ni2 = 0; ni2 < 4; ni2++) {
                int row = n_w + ni2 * 16 + b_row_in;
                int chunk = 2 * s + b_csel;
                ldsm_x4(bf[ni2], Bbase + row * 256 + ((chunk ^ jr) << 4));
            }
#pragma unroll
            for (int mi = 0; mi < 2; mi++)
#pragma unroll
                for (int ni = 0; ni < 8; ni++) {
                    int ni2 = ni >> 1;
                    uint32_t b0 = (ni & 1) ? bf[ni2][2] : bf[ni2][0];
                    uint32_t b1 = (ni & 1) ? bf[ni2][3] : bf[ni2][1];
                    mma_bf16(d[mi][ni], a[mi], b0, b1);
                }
        }
    }

    const float* bsh = reinterpret_cast<const float*>(sm + OFF_BIAS);
    int gid = lane >> 2;
    int tig = lane & 3;
#pragma unroll
    for (int mi = 0; mi < 2; mi++) {
#pragma unroll
        for (int ni = 0; ni < 8; ni++) {
            int col = n_w + ni * 8 + tig * 2;
            float b0 = bsh[col], b1 = bsh[col + 1];
            int r1 = row0 + m_w + mi * 16 + gid;
            int r2 = r1 + 8;
            if (r1 < M) {
                float2 v = make_float2(d[mi][ni][0] + b0, d[mi][ni][1] + b1);
                *reinterpret_cast<float2*>(&out[(size_t)r1 * CH + col]) = v;
            }
            if (r2 < M) {
                float2 v = make_float2(d[mi][ni][2] + b0, d[mi][ni][3] + b1);
                *reinterpret_cast<float2*>(&out[(size_t)r2 * CH + col]) = v;
            }
        }
    }
}

// ---------------- launch -----------------------------------------------------
extern "C" void kernel_launch(void* const* d_in, const int* in_sizes, int n_in,
                              void* d_out, int out_size) {
    const float* x  = (const float*)d_in[0];
    const int*   ei = (const int*)d_in[1];
    const float* W  = (const float*)d_in[2];
    const float* b  = (const float*)d_in[3];
    float* out = (float*)d_out;

    int n_nodes = in_sizes[0] / CH;
    int n_edges = in_sizes[1] / 2;
    int nblk = (n_nodes + SCAN_CHUNK - 1) / SCAN_CHUNK;

    cudaFuncSetAttribute(gemm_mma_kernel,
                         cudaFuncAttributeMaxDynamicSharedMemorySize, SMEM_DYN);

    int init_threads = n_nodes * (CH / 4);   // widest task
    init_kernel<<<(init_threads + 255) / 256, 256>>>(x, W, n_nodes);
    hist_kernel<<<(n_edges + 255) / 256, 256>>>(ei, n_edges);
    partial_kernel<<<nblk, 256>>>(n_nodes, nblk);
    scan_final_kernel<<<nblk, 256>>>(n_nodes);
    scatter_idx_kernel<<<(n_edges + 255) / 256, 256>>>(ei, n_edges);

    int agg_blocks = (n_nodes * 32 + 255) / 256;
    agg_kernel<<<agg_blocks, 256>>>(x, n_nodes);

    int gm_blocks = (n_nodes + 127) / 128;
    gemm_mma_kernel<<<gm_blocks, 256, SMEM_DYN>>>(b, out, n_nodes);
}

// round 14
// speedup vs baseline: 1.0611x; 1.0611x over previous
#include <cuda_runtime.h>
#include <cuda_bf16.h>
#include <cstdint>

#define MAX_NODES 50000
#define MAX_EDGES 640000
#define CH 128
#define SCAN_CHUNK 1024

// ---------------- scratch (no allocs allowed -> device globals) -------------
__device__ __nv_bfloat16 g_hhi[(size_t)MAX_NODES * CH];
__device__ __nv_bfloat16 g_hlo[(size_t)MAX_NODES * CH];
__device__ __nv_bfloat16 g_whi[CH * CH];
__device__ __nv_bfloat16 g_wlo[CH * CH];
__device__ int g_count[MAX_NODES + 4];
__device__ int g_start[MAX_NODES + 4];
__device__ int g_epos[MAX_EDGES];
__device__ int g_scol[MAX_EDGES];
__device__ int g_bsum[128];
__device__ int g_boff[128];
__device__ int g_done;

// ---------------- kernel 1: fused init (zero counts + W split + done reset) --
__global__ void init_kernel(const float* __restrict__ W, int n_nodes) {
    int i = blockIdx.x * blockDim.x + threadIdx.x;
    int stride = gridDim.x * blockDim.x;
    for (int k = i; k < n_nodes + 4; k += stride) g_count[k] = 0;
    if (i < CH * CH) {
        float w = W[i];
        __nv_bfloat16 hi = __float2bfloat16(w);
        g_whi[i] = hi;
        g_wlo[i] = __float2bfloat16(w - __bfloat162float(hi));
    }
    if (i == 0) g_done = 0;
}

// ---------------- kernel 2: histogram + record intra-segment position --------
__global__ void hist_kernel(const int* __restrict__ edge_index, int n_edges) {
    int e = blockIdx.x * blockDim.x + threadIdx.x;
    if (e < n_edges) {
        int r = __ldg(&edge_index[e]);
        g_epos[e] = atomicAdd(&g_count[r], 1);
    }
}

// ---------------- kernel 3: partial sums + fused block-sum scan --------------
__global__ void partial_kernel(int n_nodes, int nblk) {
    __shared__ int wsum[8];
    __shared__ int sh_last;
    __shared__ int sh[128];
    int t = threadIdx.x;
    int base = blockIdx.x * SCAN_CHUNK + t * 4;
    int s = 0;
    if (base < n_nodes) {
        int4 v = *reinterpret_cast<const int4*>(&g_count[base]);
        s = v.x;
        if (base + 1 < n_nodes) s += v.y;
        if (base + 2 < n_nodes) s += v.z;
        if (base + 3 < n_nodes) s += v.w;
    }
#pragma unroll
    for (int o = 16; o > 0; o >>= 1) s += __shfl_down_sync(0xffffffffu, s, o);
    if ((t & 31) == 0) wsum[t >> 5] = s;
    __syncthreads();
    if (t < 8) {
        int v = wsum[t];
#pragma unroll
        for (int o = 4; o > 0; o >>= 1) v += __shfl_down_sync(0xffu, v, o);
        if (t == 0) {
            g_bsum[blockIdx.x] = v;
            __threadfence();
            int old = atomicAdd(&g_done, 1);
            sh_last = (old == nblk - 1) ? 1 : 0;
        }
    }
    __syncthreads();
    if (sh_last) {   // last finishing block scans the block sums
        int v = (t < nblk && t < 128) ? g_bsum[t] : 0;
        if (t < 128) sh[t] = v;
        __syncthreads();
#pragma unroll
        for (int o = 1; o < 128; o <<= 1) {
            int x = (t < 128 && t >= o) ? sh[t - o] : 0;
            __syncthreads();
            if (t < 128) sh[t] += x;
            __syncthreads();
        }
        if (t < nblk && t < 128) g_boff[t] = sh[t] - v;
    }
}

// ---------------- kernel 4: final per-block exclusive scan -> g_start --------
__global__ void scan_final_kernel(int n_nodes) {
    __shared__ int woff[8];
    int t = threadIdx.x;
    int lane = t & 31;
    int w = t >> 5;
    int base = blockIdx.x * SCAN_CHUNK + t * 4;

    int4 c = make_int4(0, 0, 0, 0);
    if (base < n_nodes) {
        c = *reinterpret_cast<const int4*>(&g_count[base]);
        if (base + 1 >= n_nodes) c.y = 0;
        if (base + 2 >= n_nodes) c.z = 0;
        if (base + 3 >= n_nodes) c.w = 0;
    }
    int tot = c.x + c.y + c.z + c.w;

    int incl = tot;
#pragma unroll
    for (int o = 1; o < 32; o <<= 1) {
        int nv = __shfl_up_sync(0xffffffffu, incl, o);
        if (lane >= o) incl += nv;
    }
    if (lane == 31) woff[w] = incl;
    __syncthreads();
    if (t < 8) {
        int v = woff[t];
        int s = v;
#pragma unroll
        for (int o = 1; o < 8; o <<= 1) {
            int nv = __shfl_up_sync(0xffu, s, o);
            if (t >= o) s += nv;
        }
        woff[t] = s - v;
    }
    __syncthreads();

    int off = g_boff[blockIdx.x] + woff[w] + (incl - tot);
    if (base < n_nodes) {
        int4 st;
        st.x = off;
        st.y = off + c.x;
        st.z = off + c.x + c.y;
        st.w = off + c.x + c.y + c.z;
        *reinterpret_cast<int4*>(&g_start[base]) = st;
    }
}

// ---------------- kernel 5: atomic-free scatter into dest-sorted order -------
__global__ void scatter_idx_kernel(const int* __restrict__ edge_index, int n_edges) {
    int e = blockIdx.x * blockDim.x + threadIdx.x;
    if (e < n_edges) {
        int r = __ldg(&edge_index[e]);
        int c = __ldg(&edge_index[n_edges + e]);
        g_scol[__ldg(&g_start[r]) + g_epos[e]] = c;
    }
}

// ---------------- kernel 6: aggregation (fp32 gather, MLP=4) -----------------
// one warp per node; lane owns 4 channels (float4); register accumulator.
__global__ __launch_bounds__(256)
void agg_kernel(const float* __restrict__ x, int n_nodes) {
    int gtid = blockIdx.x * blockDim.x + threadIdx.x;
    int node = gtid >> 5;
    int lane = threadIdx.x & 31;
    if (node >= n_nodes) return;

    const float4* x4 = reinterpret_cast<const float4*>(x);

    int s = g_start[node];
    int d = g_count[node];

    float4 acc = make_float4(0.f, 0.f, 0.f, 0.f);
    int j = 0;
    for (; j + 3 < d; j += 4) {
        int c0 = __ldg(&g_scol[s + j]);
        int c1 = __ldg(&g_scol[s + j + 1]);
        int c2 = __ldg(&g_scol[s + j + 2]);
        int c3 = __ldg(&g_scol[s + j + 3]);
        float4 v0 = x4[(size_t)c0 * (CH / 4) + lane];
        float4 v1 = x4[(size_t)c1 * (CH / 4) + lane];
        float4 v2 = x4[(size_t)c2 * (CH / 4) + lane];
        float4 v3 = x4[(size_t)c3 * (CH / 4) + lane];
        acc.x += (v0.x + v1.x) + (v2.x + v3.x);
        acc.y += (v0.y + v1.y) + (v2.y + v3.y);
        acc.z += (v0.z + v1.z) + (v2.z + v3.z);
        acc.w += (v0.w + v1.w) + (v2.w + v3.w);
    }
    for (; j < d; j++) {
        int c0 = __ldg(&g_scol[s + j]);
        float4 v0 = x4[(size_t)c0 * (CH / 4) + lane];
        acc.x += v0.x; acc.y += v0.y; acc.z += v0.z; acc.w += v0.w;
    }

    float inv = 1.f / (float)(d < 1 ? 1 : d);
    float4 xv = x4[(size_t)node * (CH / 4) + lane];
    float h0 = xv.x + acc.x * inv;
    float h1 = xv.y + acc.y * inv;
    float h2 = xv.z + acc.z * inv;
    float h3 = xv.w + acc.w * inv;

    __nv_bfloat16 b0 = __float2bfloat16(h0);
    __nv_bfloat16 b1 = __float2bfloat16(h1);
    __nv_bfloat16 b2 = __float2bfloat16(h2);
    __nv_bfloat16 b3 = __float2bfloat16(h3);
    __nv_bfloat16 l0 = __float2bfloat16(h0 - __bfloat162float(b0));
    __nv_bfloat16 l1 = __float2bfloat16(h1 - __bfloat162float(b1));
    __nv_bfloat16 l2 = __float2bfloat16(h2 - __bfloat162float(b2));
    __nv_bfloat16 l3 = __float2bfloat16(h3 - __bfloat162float(b3));

    __nv_bfloat162* hhi2 = reinterpret_cast<__nv_bfloat162*>(g_hhi);
    __nv_bfloat162* hlo2 = reinterpret_cast<__nv_bfloat162*>(g_hlo);
    size_t base = (size_t)node * (CH / 2) + lane * 2;
    hhi2[base + 0] = __halves2bfloat162(b0, b1);
    hhi2[base + 1] = __halves2bfloat162(b2, b3);
    hlo2[base + 0] = __halves2bfloat162(l0, l1);
    hlo2[base + 1] = __halves2bfloat162(l2, l3);
}

// ---------------- kernel 7: HMMA bf16-split GEMM (proven R10) ----------------
#define OFF_AHI 0
#define OFF_ALO 32768
#define OFF_WHI 65536
#define OFF_WLO 98304
#define OFF_BIAS 131072
#define SMEM_DYN (131072 + 512)

__device__ __forceinline__ uint32_t smem_u32(const void* p) {
    uint32_t a;
    asm("{ .reg .u64 t; cvta.to.shared.u64 t, %1; cvt.u32.u64 %0, t; }" : "=r"(a) : "l"(p));
    return a;
}

__device__ __forceinline__ void ldsm_x4(uint32_t* r, uint32_t addr) {
    asm volatile("ldmatrix.sync.aligned.m8n8.x4.shared.b16 {%0,%1,%2,%3}, [%4];"
                 : "=r"(r[0]), "=r"(r[1]), "=r"(r[2]), "=r"(r[3]) : "r"(addr));
}

__device__ __forceinline__ void mma_bf16(float* d, const uint32_t* a, uint32_t b0, uint32_t b1) {
    asm volatile(
        "mma.sync.aligned.m16n8k16.row.col.f32.bf16.bf16.f32 "
        "{%0,%1,%2,%3}, {%4,%5,%6,%7}, {%8,%9}, {%0,%1,%2,%3};"
        : "+f"(d[0]), "+f"(d[1]), "+f"(d[2]), "+f"(d[3])
        : "r"(a[0]), "r"(a[1]), "r"(a[2]), "r"(a[3]), "r"(b0), "r"(b1));
}

__global__ __launch_bounds__(256, 1)
void gemm_mma_kernel(const float* __restrict__ bias, float* __restrict__ out, int M) {
    extern __shared__ char sm[];
    uint32_t sbase = smem_u32(sm);

    int tid = threadIdx.x;
    int wid = tid >> 5;
    int lane = tid & 31;
    int row0 = blockIdx.x * 128;

    const uint4* hhi4 = reinterpret_cast<const uint4*>(g_hhi);
    const uint4* hlo4 = reinterpret_cast<const uint4*>(g_hlo);
    const uint4* whi4 = reinterpret_cast<const uint4*>(g_whi);
    const uint4* wlo4 = reinterpret_cast<const uint4*>(g_wlo);
    const uint4 zero4 = make_uint4(0, 0, 0, 0);

#pragma unroll 4
    for (int i = tid; i < 2048; i += 256) {
        int row = i >> 4;
        int c = i & 15;
        uint32_t sw = (uint32_t)row * 256 + (uint32_t)((c ^ (row & 7)) << 4);
        int gr = row0 + row;
        uint4 vh = zero4, vl = zero4;
        if (gr < M) {
            size_t gidx = (size_t)gr * 16 + c;
            vh = hhi4[gidx];
            vl = hlo4[gidx];
        }
        *reinterpret_cast<uint4*>(sm + OFF_AHI + sw) = vh;
        *reinterpret_cast<uint4*>(sm + OFF_ALO + sw) = vl;
        size_t widx = (size_t)row * 16 + c;
        *reinterpret_cast<uint4*>(sm + OFF_WHI + sw) = whi4[widx];
        *reinterpret_cast<uint4*>(sm + OFF_WLO + sw) = wlo4[widx];
    }
    if (tid < CH) *reinterpret_cast<float*>(sm + OFF_BIAS + tid * 4) = bias[tid];
    __syncthreads();

    int m_w = (wid & 3) * 32;
    int n_w = (wid >> 2) * 64;

    int jr = lane & 7;
    int a_row_in = (((lane >> 3) & 1) << 3) + jr;
    int a_csel = lane >> 4;
    int b_row_in = ((lane >> 4) << 3) + jr;
    int b_csel = (lane >> 3) & 1;

    float d[2][8][4];
#pragma unroll
    for (int mi = 0; mi < 2; mi++)
#pragma unroll
        for (int ni = 0; ni < 8; ni++)
#pragma unroll
            for (int k = 0; k < 4; k++) d[mi][ni][k] = 0.f;

#pragma unroll
    for (int t = 0; t < 3; t++) {
        uint32_t Abase = sbase + (t == 2 ? OFF_ALO : OFF_AHI);
        uint32_t Bbase = sbase + (t == 1 ? OFF_WLO : OFF_WHI);
#pragma unroll
        for (int s = 0; s < 8; s++) {
            uint32_t a[2][4];
#pragma unroll
            for (int mi = 0; mi < 2; mi++) {
                int row = m_w + mi * 16 + a_row_in;
                int chunk = 2 * s + a_csel;
                ldsm_x4(a[mi], Abase + row * 256 + ((chunk ^ jr) << 4));
            }
            uint32_t bf[4][4];
#pragma unroll
            for (int ni2 = 0; ni2 < 4; ni2++) {
                int row = n_w + ni2 * 16 + b_row_in;
                int chunk = 2 * s + b_csel;
                ldsm_x4(bf[ni2], Bbase + row * 256 + ((chunk ^ jr) << 4));
            }
#pragma unroll
            for (int mi = 0; mi < 2; mi++)
#pragma unroll
                for (int ni = 0; ni < 8; ni++) {
                    int ni2 = ni >> 1;
                    uint32_t b0 = (ni & 1) ? bf[ni2][2] : bf[ni2][0];
                    uint32_t b1 = (ni & 1) ? bf[ni2][3] : bf[ni2][1];
                    mma_bf16(d[mi][ni], a[mi], b0, b1);
                }
        }
    }

    const float* bsh = reinterpret_cast<const float*>(sm + OFF_BIAS);
    int gid = lane >> 2;
    int tig = lane & 3;
#pragma unroll
    for (int mi = 0; mi < 2; mi++) {
#pragma unroll
        for (int ni = 0; ni < 8; ni++) {
            int col = n_w + ni * 8 + tig * 2;
            float b0 = bsh[col], b1 = bsh[col + 1];
            int r1 = row0 + m_w + mi * 16 + gid;
            int r2 = r1 + 8;
            if (r1 < M) {
                float2 v = make_float2(d[mi][ni][0] + b0, d[mi][ni][1] + b1);
                *reinterpret_cast<float2*>(&out[(size_t)r1 * CH + col]) = v;
            }
            if (r2 < M) {
                float2 v = make_float2(d[mi][ni][2] + b0, d[mi][ni][3] + b1);
                *reinterpret_cast<float2*>(&out[(size_t)r2 * CH + col]) = v;
            }
        }
    }
}

// ---------------- launch -----------------------------------------------------
extern "C" void kernel_launch(void* const* d_in, const int* in_sizes, int n_in,
                              void* d_out, int out_size) {
    const float* x  = (const float*)d_in[0];
    const int*   ei = (const int*)d_in[1];
    const float* W  = (const float*)d_in[2];
    const float* b  = (const float*)d_in[3];
    float* out = (float*)d_out;

    int n_nodes = in_sizes[0] / CH;
    int n_edges = in_sizes[1] / 2;
    int nblk = (n_nodes + SCAN_CHUNK - 1) / SCAN_CHUNK;

    cudaFuncSetAttribute(gemm_mma_kernel,
                         cudaFuncAttributeMaxDynamicSharedMemorySize, SMEM_DYN);

    init_kernel<<<98, 512>>>(W, n_nodes);
    hist_kernel<<<(n_edges + 255) / 256, 256>>>(ei, n_edges);
    partial_kernel<<<nblk, 256>>>(n_nodes, nblk);
    scan_final_kernel<<<nblk, 256>>>(n_nodes);
    scatter_idx_kernel<<<(n_edges + 255) / 256, 256>>>(ei, n_edges);

    int agg_blocks = (n_nodes * 32 + 255) / 256;
    agg_kernel<<<agg_blocks, 256>>>(x, n_nodes);

    int gm_blocks = (n_nodes + 127) / 128;
    gemm_mma_kernel<<<gm_blocks, 256, SMEM_DYN>>>(b, out, n_nodes);
}